// round 11
// baseline (speedup 1.0000x reference)
// R11: scan x-prefetch pipelined 2 steps deep (hide DRAM latency) + split
// MMA accumulator chains (2x4 instead of 8 deep). Rest unchanged from R10.
#include <cuda_runtime.h>
#include <cuda_fp16.h>
#include <cstdint>
#include <cstddef>

#define T_  512
#define B_  128
#define E_  300
#define H_  128
#define G4  512
#define KP  320
#define M_  (T_*B_)
#define N_  1024
#define FC1_ 256
#define C_  5

__device__ __half g_xh[(size_t)M_ * KP];
__device__ __half g_wcat[(size_t)N_ * KP];    // permuted rows
__device__ __half g_xg[(size_t)N_ * M_];      // fp16 preacts+bias, layout [n_perm][t*B+b]
__device__ float  g_hf[(size_t)T_ * B_ * H_];
__device__ float  g_hb[(size_t)T_ * B_ * H_];

__host__ __device__ __forceinline__ int perm_src(int p) {
    int r = p & 15;
    int g = ((r >> 3) << 1) | (r & 1);
    int u = (p >> 4) * 4 + ((r >> 1) & 3);
    return g * 128 + u;
}

// ---------------- prep ----------------
__global__ void prep_x(const float* __restrict__ x) {
    int m = blockIdx.x * 2 + (threadIdx.x >= KP);
    int t = m >> 7;
    int b = m & 127;
    int e = threadIdx.x >= KP ? threadIdx.x - KP : threadIdx.x;
    float v = (e < E_) ? x[((size_t)b * T_ + t) * E_ + e] : 0.f;
    g_xh[(size_t)m * KP + e] = __float2half_rn(v);
}

__global__ void prep_w(const float* __restrict__ wf, const float* __restrict__ wb) {
    int n = blockIdx.x;
    int e = threadIdx.x;
    int src = perm_src(n & 511);
    float v = 0.f;
    if (e < E_) v = (n < G4) ? wf[(size_t)src * E_ + e] : wb[(size_t)src * E_ + e];
    g_wcat[(size_t)n * KP + e] = __float2half_rn(v);
}

// ---------------- input GEMM ----------------
#define BM 128
#define BN 64
#define BK 32
#define SSTR (BK + 8)

__global__ __launch_bounds__(256) void gemm_hmma(
    const float* __restrict__ bih_f, const float* __restrict__ bhh_f,
    const float* __restrict__ bih_b, const float* __restrict__ bhh_b) {
    __shared__ __half As[2][BM][SSTR];
    __shared__ __half Bs[2][BN][SSTR];

    int tid  = threadIdx.x;
    int wid  = tid >> 5;
    int lane = tid & 31;
    int wm   = wid >> 1;
    int wn   = wid & 1;
    int bm   = blockIdx.y * BM;
    int bn   = blockIdx.x * BN;

    float acc[2][4][4];
#pragma unroll
    for (int i = 0; i < 2; i++)
#pragma unroll
        for (int j = 0; j < 4; j++)
#pragma unroll
            for (int k = 0; k < 4; k++) acc[i][j][k] = 0.f;

    int ar = tid >> 2;
    int ac = (tid & 3) * 8;

    uint4 ra0, ra1, rb0;
    {
        ra0 = *(const uint4*)&g_xh[(size_t)(bm + ar)      * KP + ac];
        ra1 = *(const uint4*)&g_xh[(size_t)(bm + 64 + ar) * KP + ac];
        rb0 = *(const uint4*)&g_wcat[(size_t)(bn + ar)    * KP + ac];
        *(uint4*)&As[0][ar][ac]      = ra0;
        *(uint4*)&As[0][64 + ar][ac] = ra1;
        *(uint4*)&Bs[0][ar][ac]      = rb0;
    }
    __syncthreads();

    const int NIT = KP / BK;
    for (int it = 0; it < NIT; ++it) {
        int cur = it & 1;
        bool pf = (it + 1 < NIT);
        if (pf) {
            int k0 = (it + 1) * BK;
            ra0 = *(const uint4*)&g_xh[(size_t)(bm + ar)      * KP + k0 + ac];
            ra1 = *(const uint4*)&g_xh[(size_t)(bm + 64 + ar) * KP + k0 + ac];
            rb0 = *(const uint4*)&g_wcat[(size_t)(bn + ar)    * KP + k0 + ac];
        }
#pragma unroll
        for (int kk = 0; kk < 2; ++kk) {
            uint32_t a[2][4], bf[4][2];
#pragma unroll
            for (int mf = 0; mf < 2; ++mf) {
                int row = wm * 32 + mf * 16 + (lane & 15);
                int ko  = kk * 16 + (lane >> 4) * 8;
                unsigned sa = (unsigned)__cvta_generic_to_shared(&As[cur][row][ko]);
                asm volatile("ldmatrix.sync.aligned.m8n8.x4.shared.b16 {%0,%1,%2,%3}, [%4];"
                             : "=r"(a[mf][0]), "=r"(a[mf][1]), "=r"(a[mf][2]), "=r"(a[mf][3])
                             : "r"(sa));
            }
#pragma unroll
            for (int nf = 0; nf < 4; ++nf) {
                int row = wn * 32 + nf * 8 + (lane & 7);
                int ko  = kk * 16 + ((lane >> 3) & 1) * 8;
                unsigned sb = (unsigned)__cvta_generic_to_shared(&Bs[cur][row][ko]);
                asm volatile("ldmatrix.sync.aligned.m8n8.x2.shared.b16 {%0,%1}, [%2];"
                             : "=r"(bf[nf][0]), "=r"(bf[nf][1])
                             : "r"(sb));
            }
#pragma unroll
            for (int mf = 0; mf < 2; ++mf)
#pragma unroll
                for (int nf = 0; nf < 4; ++nf)
                    asm volatile(
                        "mma.sync.aligned.m16n8k16.row.col.f32.f16.f16.f32 "
                        "{%0,%1,%2,%3},{%4,%5,%6,%7},{%8,%9},{%0,%1,%2,%3};"
                        : "+f"(acc[mf][nf][0]), "+f"(acc[mf][nf][1]),
                          "+f"(acc[mf][nf][2]), "+f"(acc[mf][nf][3])
                        : "r"(a[mf][0]), "r"(a[mf][1]), "r"(a[mf][2]), "r"(a[mf][3]),
                          "r"(bf[nf][0]), "r"(bf[nf][1]));
        }
        __syncthreads();
        if (pf) {
            int nxt = 1 - cur;
            *(uint4*)&As[nxt][ar][ac]      = ra0;
            *(uint4*)&As[nxt][64 + ar][ac] = ra1;
            *(uint4*)&Bs[nxt][ar][ac]      = rb0;
        }
        __syncthreads();
    }

    float bb[4][2];
#pragma unroll
    for (int nf = 0; nf < 4; ++nf) {
#pragma unroll
        for (int h = 0; h < 2; ++h) {
            int col = bn + wn * 32 + nf * 8 + (lane & 3) * 2 + h;
            int src = perm_src(col & 511);
            bb[nf][h] = (col < G4) ? (bih_f[src] + bhh_f[src])
                                   : (bih_b[src] + bhh_b[src]);
        }
    }
#pragma unroll
    for (int mf = 0; mf < 2; ++mf)
#pragma unroll
        for (int nf = 0; nf < 4; ++nf) {
            int r = bm + wm * 32 + mf * 16 + (lane >> 2);
            int c = bn + wn * 32 + nf * 8 + (lane & 3) * 2;
            g_xg[(size_t)c       * M_ + r]     = __float2half_rn(acc[mf][nf][0] + bb[nf][0]);
            g_xg[(size_t)(c + 1) * M_ + r]     = __float2half_rn(acc[mf][nf][1] + bb[nf][1]);
            g_xg[(size_t)c       * M_ + r + 8] = __float2half_rn(acc[mf][nf][2] + bb[nf][0]);
            g_xg[(size_t)(c + 1) * M_ + r + 8] = __float2half_rn(acc[mf][nf][3] + bb[nf][1]);
        }
}

// ---------------- tensor-core LSTM scan (batch on n) ----------------
__device__ __forceinline__ float tanh_t(float x) {
    float r; asm("tanh.approx.f32 %0, %1;" : "=f"(r) : "f"(x)); return r;
}
__device__ __forceinline__ float sig_t(float x) {
    return fmaf(tanh_t(0.5f * x), 0.5f, 0.5f);
}

#define NB 8

__global__ __launch_bounds__(512, 1) void lstm_scan_mma(
    const float* __restrict__ Whh_f, const float* __restrict__ Whh_b) {
    __shared__ __align__(16) __half sh[2][H_][NB];

    int tid = threadIdx.x;
    int w   = tid >> 5;
    int l   = tid & 31;
    int c   = l & 3;
    int rg  = l >> 2;
    int dir = blockIdx.x >> 4;
    int b0  = (blockIdx.x & 15) * NB;
    const float* Whh = dir ? Whh_b : Whh_f;
    float* hout = dir ? g_hb : g_hf;
    int myp = rg & 1;
    int bat = c * 2 + myp;
    int uloc = rg >> 1;

    // ---- W fragments (A operand, m16k16), one-time ----
    uint32_t afr[2][8][4];
#pragma unroll
    for (int mt = 0; mt < 2; mt++) {
        int tau = w * 2 + mt;
        int o1 = (myp)     * 128 + tau * 4 + uloc;
        int o2 = (myp + 2) * 128 + tau * 4 + uloc;
        const float* w1 = Whh + (size_t)o1 * H_;
        const float* w2 = Whh + (size_t)o2 * H_;
#pragma unroll
        for (int kt = 0; kt < 8; kt++) {
            int k = kt * 16 + c * 2;
            float2 p0 = *(const float2*)&w1[k];
            float2 p1 = *(const float2*)&w2[k];
            float2 p2 = *(const float2*)&w1[k + 8];
            float2 p3 = *(const float2*)&w2[k + 8];
            __half2 h0 = __floats2half2_rn(p0.x, p0.y);
            __half2 h1 = __floats2half2_rn(p1.x, p1.y);
            __half2 h2 = __floats2half2_rn(p2.x, p2.y);
            __half2 h3 = __floats2half2_rn(p3.x, p3.y);
            afr[mt][kt][0] = *(uint32_t*)&h0;
            afr[mt][kt][1] = *(uint32_t*)&h1;
            afr[mt][kt][2] = *(uint32_t*)&h2;
            afr[mt][kt][3] = *(uint32_t*)&h3;
        }
    }

    for (int i = tid; i < 2 * H_ * NB; i += 512) ((__half*)sh)[i] = __float2half(0.f);

    // x pipeline, 2 steps deep: xr[s&1] holds step s's preacts
    const size_t nbase = (size_t)(dir * G4 + w * 32);
    uint32_t xr[2][2][2];
#pragma unroll
    for (int ps = 0; ps < 2; ps++) {
        int tt = dir ? (T_ - 1 - ps) : ps;
        size_t mo = (size_t)tt * B_ + b0 + c * 2;
#pragma unroll
        for (int mt = 0; mt < 2; mt++) {
            xr[ps][mt][0] = *(const uint32_t*)&g_xg[(nbase + mt * 16 + rg)     * M_ + mo];
            xr[ps][mt][1] = *(const uint32_t*)&g_xg[(nbase + mt * 16 + rg + 8) * M_ + mo];
        }
    }

    float cst[2] = {0.f, 0.f};
    __syncthreads();

    for (int s = 0; s < T_; ++s) {
        int tt = dir ? (T_ - 1 - s) : s;
        int pb = s & 1;

        // D init = x preacts (consume pipeline slot pb)
        float d[2][4], e2[2][4];
#pragma unroll
        for (int mt = 0; mt < 2; mt++) {
            float2 lo = __half22float2(*(__half2*)&xr[pb][mt][0]);
            float2 hi = __half22float2(*(__half2*)&xr[pb][mt][1]);
            d[mt][0] = lo.x; d[mt][1] = lo.y; d[mt][2] = hi.x; d[mt][3] = hi.y;
            e2[mt][0] = 0.f; e2[mt][1] = 0.f; e2[mt][2] = 0.f; e2[mt][3] = 0.f;
        }

        // B fragments (h), shared by both m-tiles
        uint32_t bfr[8][2];
#pragma unroll
        for (int kt = 0; kt < 8; kt++) {
            unsigned sb = (unsigned)__cvta_generic_to_shared(&sh[s & 1][kt * 16 + (l & 15)][0]);
            asm volatile("ldmatrix.sync.aligned.m8n8.x2.trans.shared.b16 {%0,%1}, [%2];"
                         : "=r"(bfr[kt][0]), "=r"(bfr[kt][1]) : "r"(sb));
        }

        // prefetch x for step s+2 into slot pb (freed by D-init above)
        if (s + 2 < T_) {
            int tn = dir ? (T_ - 3 - s) : (s + 2);
            size_t mo = (size_t)tn * B_ + b0 + c * 2;
#pragma unroll
            for (int mt = 0; mt < 2; mt++) {
                xr[pb][mt][0] = *(const uint32_t*)&g_xg[(nbase + mt * 16 + rg)     * M_ + mo];
                xr[pb][mt][1] = *(const uint32_t*)&g_xg[(nbase + mt * 16 + rg + 8) * M_ + mo];
            }
        }

        // two 4-deep accumulator chains per m-tile (d: kt 0-3, e2: kt 4-7)
#pragma unroll
        for (int kt = 0; kt < 4; kt++) {
#pragma unroll
            for (int mt = 0; mt < 2; mt++) {
                asm volatile(
                    "mma.sync.aligned.m16n8k16.row.col.f32.f16.f16.f32 "
                    "{%0,%1,%2,%3},{%4,%5,%6,%7},{%8,%9},{%0,%1,%2,%3};"
                    : "+f"(d[mt][0]), "+f"(d[mt][1]), "+f"(d[mt][2]), "+f"(d[mt][3])
                    : "r"(afr[mt][kt][0]), "r"(afr[mt][kt][1]),
                      "r"(afr[mt][kt][2]), "r"(afr[mt][kt][3]),
                      "r"(bfr[kt][0]), "r"(bfr[kt][1]));
                asm volatile(
                    "mma.sync.aligned.m16n8k16.row.col.f32.f16.f16.f32 "
                    "{%0,%1,%2,%3},{%4,%5,%6,%7},{%8,%9},{%0,%1,%2,%3};"
                    : "+f"(e2[mt][0]), "+f"(e2[mt][1]), "+f"(e2[mt][2]), "+f"(e2[mt][3])
                    : "r"(afr[mt][kt + 4][0]), "r"(afr[mt][kt + 4][1]),
                      "r"(afr[mt][kt + 4][2]), "r"(afr[mt][kt + 4][3]),
                      "r"(bfr[kt + 4][0]), "r"(bfr[kt + 4][1]));
            }
        }
#pragma unroll
        for (int mt = 0; mt < 2; mt++) {
            d[mt][0] += e2[mt][0]; d[mt][1] += e2[mt][1];
            d[mt][2] += e2[mt][2]; d[mt][3] += e2[mt][3];
        }

        // elementwise
#pragma unroll
        for (int mt = 0; mt < 2; mt++) {
            float alo_b0 = sig_t(d[mt][0]);
            float alo_b1 = sig_t(d[mt][1]);
            float ahi_b0 = myp ? sig_t(d[mt][2]) : tanh_t(d[mt][2]);
            float ahi_b1 = myp ? sig_t(d[mt][3]) : tanh_t(d[mt][3]);
            float mine_lo = myp ? alo_b1 : alo_b0;
            float mine_hi = myp ? ahi_b1 : ahi_b0;
            float send_lo = myp ? alo_b0 : alo_b1;
            float send_hi = myp ? ahi_b0 : ahi_b1;
            float rec_lo = __shfl_xor_sync(0xffffffffu, send_lo, 4);
            float rec_hi = __shfl_xor_sync(0xffffffffu, send_hi, 4);
            float ii = myp ? rec_lo  : mine_lo;
            float gg = myp ? rec_hi  : mine_hi;
            float ff = myp ? mine_lo : rec_lo;
            float oo = myp ? mine_hi : rec_hi;
            float cn = fmaf(ff, cst[mt], ii * gg);
            cst[mt] = cn;
            float hh = oo * tanh_t(cn);
            int unit = (w * 2 + mt) * 4 + uloc;
            sh[(s + 1) & 1][unit][bat] = __float2half_rn(hh);
            hout[((size_t)tt * B_ + b0 + bat) * H_ + unit] = hh;
        }
        __syncthreads();
    }
}

// ---------------- attention pooling + MLP head ----------------
__global__ __launch_bounds__(256) void attn_mlp(
    const float* __restrict__ attn_w, const float* __restrict__ attn_b,
    const float* __restrict__ fc1_w, const float* __restrict__ fc1_b,
    const float* __restrict__ fc2_w, const float* __restrict__ fc2_b,
    float* __restrict__ out) {
    __shared__ float aw[256];
    __shared__ float sl[512];
    __shared__ float red[256];
    __shared__ float sp[256];
    __shared__ float sh1[256];

    int b = blockIdx.x, tid = threadIdx.x;
    aw[tid] = attn_w[tid];
    __syncthreads();
    float ab = attn_b[0];

#pragma unroll
    for (int r = 0; r < 2; r++) {
        int t = tid + r * 256;
        const float4* pf = (const float4*)&g_hf[((size_t)t * B_ + b) * H_];
        const float4* pb = (const float4*)&g_hb[((size_t)t * B_ + b) * H_];
        const float4* wf = (const float4*)aw;
        const float4* wb = (const float4*)(aw + 128);
        float acc = 0.f;
#pragma unroll 8
        for (int qq = 0; qq < 32; qq++) {
            float4 a = pf[qq]; float4 w = wf[qq];
            acc += a.x * w.x + a.y * w.y + a.z * w.z + a.w * w.w;
        }
#pragma unroll 8
        for (int qq = 0; qq < 32; qq++) {
            float4 a = pb[qq]; float4 w = wb[qq];
            acc += a.x * w.x + a.y * w.y + a.z * w.z + a.w * w.w;
        }
        sl[t] = acc + ab;
    }
    __syncthreads();

    red[tid] = fmaxf(sl[tid], sl[tid + 256]);
    __syncthreads();
    for (int st = 128; st > 0; st >>= 1) {
        if (tid < st) red[tid] = fmaxf(red[tid], red[tid + st]);
        __syncthreads();
    }
    float mx = red[0];
    __syncthreads();
    float e0 = __expf(sl[tid] - mx), e1 = __expf(sl[tid + 256] - mx);
    sl[tid] = e0; sl[tid + 256] = e1;
    red[tid] = e0 + e1;
    __syncthreads();
    for (int st = 128; st > 0; st >>= 1) {
        if (tid < st) red[tid] += red[tid + st];
        __syncthreads();
    }
    float inv = 1.f / red[0];
    __syncthreads();

    {
        const float* src = (tid < 128) ? g_hf : g_hb;
        int u = tid & 127;
        float a0 = 0, a1 = 0, a2 = 0, a3 = 0;
        for (int t = 0; t < 512; t += 4) {
            a0 += sl[t    ] * src[((size_t)(t    ) * B_ + b) * H_ + u];
            a1 += sl[t + 1] * src[((size_t)(t + 1) * B_ + b) * H_ + u];
            a2 += sl[t + 2] * src[((size_t)(t + 2) * B_ + b) * H_ + u];
            a3 += sl[t + 3] * src[((size_t)(t + 3) * B_ + b) * H_ + u];
        }
        sp[tid] = (a0 + a1 + a2 + a3) * inv;
    }
    __syncthreads();

    {
        const float4* w = (const float4*)&fc1_w[(size_t)tid * 256];
        const float4* p = (const float4*)sp;
        float acc = fc1_b[tid];
#pragma unroll 8
        for (int qq = 0; qq < 64; qq++) {
            float4 a = p[qq]; float4 ww = w[qq];
            acc += a.x * ww.x + a.y * ww.y + a.z * ww.z + a.w * ww.w;
        }
        sh1[tid] = fmaxf(acc, 0.f);
    }
    __syncthreads();

    if (tid < 160) {
        int cc = tid >> 5, lane = tid & 31;
        float acc = 0.f;
        for (int qq = lane; qq < 256; qq += 32) acc += sh1[qq] * fc2_w[(size_t)cc * 256 + qq];
#pragma unroll
        for (int o = 16; o > 0; o >>= 1) acc += __shfl_down_sync(0xffffffffu, acc, o);
        if (lane == 0) out[b * C_ + cc] = acc + fc2_b[cc];
    }
}

// ---------------- launch ----------------
extern "C" void kernel_launch(void* const* d_in, const int* in_sizes, int n_in,
                              void* d_out, int out_size) {
    const float* x      = (const float*)d_in[0];
    const float* Wih_f  = (const float*)d_in[1];
    const float* Whh_f  = (const float*)d_in[2];
    const float* bih_f  = (const float*)d_in[3];
    const float* bhh_f  = (const float*)d_in[4];
    const float* Wih_b  = (const float*)d_in[5];
    const float* Whh_b  = (const float*)d_in[6];
    const float* bih_b  = (const float*)d_in[7];
    const float* bhh_b  = (const float*)d_in[8];
    const float* attn_w = (const float*)d_in[9];
    const float* attn_b = (const float*)d_in[10];
    const float* fc1_w  = (const float*)d_in[11];
    const float* fc1_b  = (const float*)d_in[12];
    const float* fc2_w  = (const float*)d_in[13];
    const float* fc2_b  = (const float*)d_in[14];
    float* out = (float*)d_out;

    prep_x<<<M_ / 2, 2 * KP>>>(x);
    prep_w<<<N_, KP>>>(Wih_f, Wih_b);
    gemm_hmma<<<dim3(N_ / BN, M_ / BM), 256>>>(bih_f, bhh_f, bih_b, bhh_b);

    lstm_scan_mma<<<32, 512>>>(Whh_f, Whh_b);

    attn_mlp<<<B_, 256>>>(attn_w, attn_b, fc1_w, fc1_b, fc2_w, fc2_b, out);
}

// round 13
// speedup vs baseline: 1.3792x; 1.3792x over previous
// R13: resubmit of R12 (broker flake — never executed). R10 scan + ONE
// register-neutral fix: x prefetch hoisted before the MMA block.
#include <cuda_runtime.h>
#include <cuda_fp16.h>
#include <cstdint>
#include <cstddef>

#define T_  512
#define B_  128
#define E_  300
#define H_  128
#define G4  512
#define KP  320
#define M_  (T_*B_)
#define N_  1024
#define FC1_ 256
#define C_  5

__device__ __half g_xh[(size_t)M_ * KP];
__device__ __half g_wcat[(size_t)N_ * KP];    // permuted rows
__device__ __half g_xg[(size_t)N_ * M_];      // fp16 preacts+bias, layout [n_perm][t*B+b]
__device__ float  g_hf[(size_t)T_ * B_ * H_];
__device__ float  g_hb[(size_t)T_ * B_ * H_];

__host__ __device__ __forceinline__ int perm_src(int p) {
    int r = p & 15;
    int g = ((r >> 3) << 1) | (r & 1);
    int u = (p >> 4) * 4 + ((r >> 1) & 3);
    return g * 128 + u;
}

// ---------------- prep ----------------
__global__ void prep_x(const float* __restrict__ x) {
    int m = blockIdx.x * 2 + (threadIdx.x >= KP);
    int t = m >> 7;
    int b = m & 127;
    int e = threadIdx.x >= KP ? threadIdx.x - KP : threadIdx.x;
    float v = (e < E_) ? x[((size_t)b * T_ + t) * E_ + e] : 0.f;
    g_xh[(size_t)m * KP + e] = __float2half_rn(v);
}

__global__ void prep_w(const float* __restrict__ wf, const float* __restrict__ wb) {
    int n = blockIdx.x;
    int e = threadIdx.x;
    int src = perm_src(n & 511);
    float v = 0.f;
    if (e < E_) v = (n < G4) ? wf[(size_t)src * E_ + e] : wb[(size_t)src * E_ + e];
    g_wcat[(size_t)n * KP + e] = __float2half_rn(v);
}

// ---------------- input GEMM ----------------
#define BM 128
#define BN 64
#define BK 32
#define SSTR (BK + 8)

__global__ __launch_bounds__(256) void gemm_hmma(
    const float* __restrict__ bih_f, const float* __restrict__ bhh_f,
    const float* __restrict__ bih_b, const float* __restrict__ bhh_b) {
    __shared__ __half As[2][BM][SSTR];
    __shared__ __half Bs[2][BN][SSTR];

    int tid  = threadIdx.x;
    int wid  = tid >> 5;
    int lane = tid & 31;
    int wm   = wid >> 1;
    int wn   = wid & 1;
    int bm   = blockIdx.y * BM;
    int bn   = blockIdx.x * BN;

    float acc[2][4][4];
#pragma unroll
    for (int i = 0; i < 2; i++)
#pragma unroll
        for (int j = 0; j < 4; j++)
#pragma unroll
            for (int k = 0; k < 4; k++) acc[i][j][k] = 0.f;

    int ar = tid >> 2;
    int ac = (tid & 3) * 8;

    uint4 ra0, ra1, rb0;
    {
        ra0 = *(const uint4*)&g_xh[(size_t)(bm + ar)      * KP + ac];
        ra1 = *(const uint4*)&g_xh[(size_t)(bm + 64 + ar) * KP + ac];
        rb0 = *(const uint4*)&g_wcat[(size_t)(bn + ar)    * KP + ac];
        *(uint4*)&As[0][ar][ac]      = ra0;
        *(uint4*)&As[0][64 + ar][ac] = ra1;
        *(uint4*)&Bs[0][ar][ac]      = rb0;
    }
    __syncthreads();

    const int NIT = KP / BK;
    for (int it = 0; it < NIT; ++it) {
        int cur = it & 1;
        bool pf = (it + 1 < NIT);
        if (pf) {
            int k0 = (it + 1) * BK;
            ra0 = *(const uint4*)&g_xh[(size_t)(bm + ar)      * KP + k0 + ac];
            ra1 = *(const uint4*)&g_xh[(size_t)(bm + 64 + ar) * KP + k0 + ac];
            rb0 = *(const uint4*)&g_wcat[(size_t)(bn + ar)    * KP + k0 + ac];
        }
#pragma unroll
        for (int kk = 0; kk < 2; ++kk) {
            uint32_t a[2][4], bf[4][2];
#pragma unroll
            for (int mf = 0; mf < 2; ++mf) {
                int row = wm * 32 + mf * 16 + (lane & 15);
                int ko  = kk * 16 + (lane >> 4) * 8;
                unsigned sa = (unsigned)__cvta_generic_to_shared(&As[cur][row][ko]);
                asm volatile("ldmatrix.sync.aligned.m8n8.x4.shared.b16 {%0,%1,%2,%3}, [%4];"
                             : "=r"(a[mf][0]), "=r"(a[mf][1]), "=r"(a[mf][2]), "=r"(a[mf][3])
                             : "r"(sa));
            }
#pragma unroll
            for (int nf = 0; nf < 4; ++nf) {
                int row = wn * 32 + nf * 8 + (lane & 7);
                int ko  = kk * 16 + ((lane >> 3) & 1) * 8;
                unsigned sb = (unsigned)__cvta_generic_to_shared(&Bs[cur][row][ko]);
                asm volatile("ldmatrix.sync.aligned.m8n8.x2.shared.b16 {%0,%1}, [%2];"
                             : "=r"(bf[nf][0]), "=r"(bf[nf][1])
                             : "r"(sb));
            }
#pragma unroll
            for (int mf = 0; mf < 2; ++mf)
#pragma unroll
                for (int nf = 0; nf < 4; ++nf)
                    asm volatile(
                        "mma.sync.aligned.m16n8k16.row.col.f32.f16.f16.f32 "
                        "{%0,%1,%2,%3},{%4,%5,%6,%7},{%8,%9},{%0,%1,%2,%3};"
                        : "+f"(acc[mf][nf][0]), "+f"(acc[mf][nf][1]),
                          "+f"(acc[mf][nf][2]), "+f"(acc[mf][nf][3])
                        : "r"(a[mf][0]), "r"(a[mf][1]), "r"(a[mf][2]), "r"(a[mf][3]),
                          "r"(bf[nf][0]), "r"(bf[nf][1]));
        }
        __syncthreads();
        if (pf) {
            int nxt = 1 - cur;
            *(uint4*)&As[nxt][ar][ac]      = ra0;
            *(uint4*)&As[nxt][64 + ar][ac] = ra1;
            *(uint4*)&Bs[nxt][ar][ac]      = rb0;
        }
        __syncthreads();
    }

    float bb[4][2];
#pragma unroll
    for (int nf = 0; nf < 4; ++nf) {
#pragma unroll
        for (int h = 0; h < 2; ++h) {
            int col = bn + wn * 32 + nf * 8 + (lane & 3) * 2 + h;
            int src = perm_src(col & 511);
            bb[nf][h] = (col < G4) ? (bih_f[src] + bhh_f[src])
                                   : (bih_b[src] + bhh_b[src]);
        }
    }
#pragma unroll
    for (int mf = 0; mf < 2; ++mf)
#pragma unroll
        for (int nf = 0; nf < 4; ++nf) {
            int r = bm + wm * 32 + mf * 16 + (lane >> 2);
            int c = bn + wn * 32 + nf * 8 + (lane & 3) * 2;
            g_xg[(size_t)c       * M_ + r]     = __float2half_rn(acc[mf][nf][0] + bb[nf][0]);
            g_xg[(size_t)(c + 1) * M_ + r]     = __float2half_rn(acc[mf][nf][1] + bb[nf][1]);
            g_xg[(size_t)c       * M_ + r + 8] = __float2half_rn(acc[mf][nf][2] + bb[nf][0]);
            g_xg[(size_t)(c + 1) * M_ + r + 8] = __float2half_rn(acc[mf][nf][3] + bb[nf][1]);
        }
}

// ---------------- tensor-core LSTM scan (batch on n) ----------------
__device__ __forceinline__ float tanh_t(float x) {
    float r; asm("tanh.approx.f32 %0, %1;" : "=f"(r) : "f"(x)); return r;
}
__device__ __forceinline__ float sig_t(float x) {
    return fmaf(tanh_t(0.5f * x), 0.5f, 0.5f);
}

#define NB 8

__global__ __launch_bounds__(512, 1) void lstm_scan_mma(
    const float* __restrict__ Whh_f, const float* __restrict__ Whh_b) {
    __shared__ __align__(16) __half sh[2][H_][NB];

    int tid = threadIdx.x;
    int w   = tid >> 5;
    int l   = tid & 31;
    int c   = l & 3;
    int rg  = l >> 2;
    int dir = blockIdx.x >> 4;
    int b0  = (blockIdx.x & 15) * NB;
    const float* Whh = dir ? Whh_b : Whh_f;
    float* hout = dir ? g_hb : g_hf;
    int myp = rg & 1;
    int bat = c * 2 + myp;
    int uloc = rg >> 1;

    // ---- W fragments (A operand, m16k16), one-time ----
    uint32_t afr[2][8][4];
#pragma unroll
    for (int mt = 0; mt < 2; mt++) {
        int tau = w * 2 + mt;
        int o1 = (myp)     * 128 + tau * 4 + uloc;
        int o2 = (myp + 2) * 128 + tau * 4 + uloc;
        const float* w1 = Whh + (size_t)o1 * H_;
        const float* w2 = Whh + (size_t)o2 * H_;
#pragma unroll
        for (int kt = 0; kt < 8; kt++) {
            int k = kt * 16 + c * 2;
            float2 p0 = *(const float2*)&w1[k];
            float2 p1 = *(const float2*)&w2[k];
            float2 p2 = *(const float2*)&w1[k + 8];
            float2 p3 = *(const float2*)&w2[k + 8];
            __half2 h0 = __floats2half2_rn(p0.x, p0.y);
            __half2 h1 = __floats2half2_rn(p1.x, p1.y);
            __half2 h2 = __floats2half2_rn(p2.x, p2.y);
            __half2 h3 = __floats2half2_rn(p3.x, p3.y);
            afr[mt][kt][0] = *(uint32_t*)&h0;
            afr[mt][kt][1] = *(uint32_t*)&h1;
            afr[mt][kt][2] = *(uint32_t*)&h2;
            afr[mt][kt][3] = *(uint32_t*)&h3;
        }
    }

    for (int i = tid; i < 2 * H_ * NB; i += 512) ((__half*)sh)[i] = __float2half(0.f);

    const size_t nbase = (size_t)(dir * G4 + w * 32);
    uint32_t xr[2][2];
    {
        int tt = dir ? (T_ - 1) : 0;
        size_t mo = (size_t)tt * B_ + b0 + c * 2;
#pragma unroll
        for (int mt = 0; mt < 2; mt++) {
            xr[mt][0] = *(const uint32_t*)&g_xg[(nbase + mt * 16 + rg)     * M_ + mo];
            xr[mt][1] = *(const uint32_t*)&g_xg[(nbase + mt * 16 + rg + 8) * M_ + mo];
        }
    }

    float cst[2] = {0.f, 0.f};
    __syncthreads();

    for (int s = 0; s < T_; ++s) {
        int tt = dir ? (T_ - 1 - s) : s;

        // D init = x preacts (consumes xr)
        float d[2][4];
#pragma unroll
        for (int mt = 0; mt < 2; mt++) {
            float2 lo = __half22float2(*(__half2*)&xr[mt][0]);
            float2 hi = __half22float2(*(__half2*)&xr[mt][1]);
            d[mt][0] = lo.x; d[mt][1] = lo.y; d[mt][2] = hi.x; d[mt][3] = hi.y;
        }

        // prefetch next x NOW — xr slot is dead, and the MMA block below
        // gives the LDGs ~600-800 cyc of cover (register-neutral reorder)
        if (s + 1 < T_) {
            int tn = dir ? (T_ - 2 - s) : (s + 1);
            size_t mo = (size_t)tn * B_ + b0 + c * 2;
#pragma unroll
            for (int mt = 0; mt < 2; mt++) {
                xr[mt][0] = *(const uint32_t*)&g_xg[(nbase + mt * 16 + rg)     * M_ + mo];
                xr[mt][1] = *(const uint32_t*)&g_xg[(nbase + mt * 16 + rg + 8) * M_ + mo];
            }
        }

        // B fragments (h), shared by both m-tiles
        uint32_t bfr[8][2];
#pragma unroll
        for (int kt = 0; kt < 8; kt++) {
            unsigned sb = (unsigned)__cvta_generic_to_shared(&sh[s & 1][kt * 16 + (l & 15)][0]);
            asm volatile("ldmatrix.sync.aligned.m8n8.x2.trans.shared.b16 {%0,%1}, [%2];"
                         : "=r"(bfr[kt][0]), "=r"(bfr[kt][1]) : "r"(sb));
        }
#pragma unroll
        for (int mt = 0; mt < 2; mt++)
#pragma unroll
            for (int kt = 0; kt < 8; kt++)
                asm volatile(
                    "mma.sync.aligned.m16n8k16.row.col.f32.f16.f16.f32 "
                    "{%0,%1,%2,%3},{%4,%5,%6,%7},{%8,%9},{%0,%1,%2,%3};"
                    : "+f"(d[mt][0]), "+f"(d[mt][1]), "+f"(d[mt][2]), "+f"(d[mt][3])
                    : "r"(afr[mt][kt][0]), "r"(afr[mt][kt][1]),
                      "r"(afr[mt][kt][2]), "r"(afr[mt][kt][3]),
                      "r"(bfr[kt][0]), "r"(bfr[kt][1]));

        // elementwise
#pragma unroll
        for (int mt = 0; mt < 2; mt++) {
            float alo_b0 = sig_t(d[mt][0]);
            float alo_b1 = sig_t(d[mt][1]);
            float ahi_b0 = myp ? sig_t(d[mt][2]) : tanh_t(d[mt][2]);
            float ahi_b1 = myp ? sig_t(d[mt][3]) : tanh_t(d[mt][3]);
            float mine_lo = myp ? alo_b1 : alo_b0;
            float mine_hi = myp ? ahi_b1 : ahi_b0;
            float send_lo = myp ? alo_b0 : alo_b1;
            float send_hi = myp ? ahi_b0 : ahi_b1;
            float rec_lo = __shfl_xor_sync(0xffffffffu, send_lo, 4);
            float rec_hi = __shfl_xor_sync(0xffffffffu, send_hi, 4);
            float ii = myp ? rec_lo  : mine_lo;
            float gg = myp ? rec_hi  : mine_hi;
            float ff = myp ? mine_lo : rec_lo;
            float oo = myp ? mine_hi : rec_hi;
            float cn = fmaf(ff, cst[mt], ii * gg);
            cst[mt] = cn;
            float hh = oo * tanh_t(cn);
            int unit = (w * 2 + mt) * 4 + uloc;
            sh[(s + 1) & 1][unit][bat] = __float2half_rn(hh);
            hout[((size_t)tt * B_ + b0 + bat) * H_ + unit] = hh;
        }
        __syncthreads();
    }
}

// ---------------- attention pooling + MLP head ----------------
__global__ __launch_bounds__(256) void attn_mlp(
    const float* __restrict__ attn_w, const float* __restrict__ attn_b,
    const float* __restrict__ fc1_w, const float* __restrict__ fc1_b,
    const float* __restrict__ fc2_w, const float* __restrict__ fc2_b,
    float* __restrict__ out) {
    __shared__ float aw[256];
    __shared__ float sl[512];
    __shared__ float red[256];
    __shared__ float sp[256];
    __shared__ float sh1[256];

    int b = blockIdx.x, tid = threadIdx.x;
    aw[tid] = attn_w[tid];
    __syncthreads();
    float ab = attn_b[0];

#pragma unroll
    for (int r = 0; r < 2; r++) {
        int t = tid + r * 256;
        const float4* pf = (const float4*)&g_hf[((size_t)t * B_ + b) * H_];
        const float4* pb = (const float4*)&g_hb[((size_t)t * B_ + b) * H_];
        const float4* wf = (const float4*)aw;
        const float4* wb = (const float4*)(aw + 128);
        float acc = 0.f;
#pragma unroll 8
        for (int qq = 0; qq < 32; qq++) {
            float4 a = pf[qq]; float4 w = wf[qq];
            acc += a.x * w.x + a.y * w.y + a.z * w.z + a.w * w.w;
        }
#pragma unroll 8
        for (int qq = 0; qq < 32; qq++) {
            float4 a = pb[qq]; float4 w = wb[qq];
            acc += a.x * w.x + a.y * w.y + a.z * w.z + a.w * w.w;
        }
        sl[t] = acc + ab;
    }
    __syncthreads();

    red[tid] = fmaxf(sl[tid], sl[tid + 256]);
    __syncthreads();
    for (int st = 128; st > 0; st >>= 1) {
        if (tid < st) red[tid] = fmaxf(red[tid], red[tid + st]);
        __syncthreads();
    }
    float mx = red[0];
    __syncthreads();
    float e0 = __expf(sl[tid] - mx), e1 = __expf(sl[tid + 256] - mx);
    sl[tid] = e0; sl[tid + 256] = e1;
    red[tid] = e0 + e1;
    __syncthreads();
    for (int st = 128; st > 0; st >>= 1) {
        if (tid < st) red[tid] += red[tid + st];
        __syncthreads();
    }
    float inv = 1.f / red[0];
    __syncthreads();

    {
        const float* src = (tid < 128) ? g_hf : g_hb;
        int u = tid & 127;
        float a0 = 0, a1 = 0, a2 = 0, a3 = 0;
        for (int t = 0; t < 512; t += 4) {
            a0 += sl[t    ] * src[((size_t)(t    ) * B_ + b) * H_ + u];
            a1 += sl[t + 1] * src[((size_t)(t + 1) * B_ + b) * H_ + u];
            a2 += sl[t + 2] * src[((size_t)(t + 2) * B_ + b) * H_ + u];
            a3 += sl[t + 3] * src[((size_t)(t + 3) * B_ + b) * H_ + u];
        }
        sp[tid] = (a0 + a1 + a2 + a3) * inv;
    }
    __syncthreads();

    {
        const float4* w = (const float4*)&fc1_w[(size_t)tid * 256];
        const float4* p = (const float4*)sp;
        float acc = fc1_b[tid];
#pragma unroll 8
        for (int qq = 0; qq < 64; qq++) {
            float4 a = p[qq]; float4 ww = w[qq];
            acc += a.x * ww.x + a.y * ww.y + a.z * ww.z + a.w * ww.w;
        }
        sh1[tid] = fmaxf(acc, 0.f);
    }
    __syncthreads();

    if (tid < 160) {
        int cc = tid >> 5, lane = tid & 31;
        float acc = 0.f;
        for (int qq = lane; qq < 256; qq += 32) acc += sh1[qq] * fc2_w[(size_t)cc * 256 + qq];
#pragma unroll
        for (int o = 16; o > 0; o >>= 1) acc += __shfl_down_sync(0xffffffffu, acc, o);
        if (lane == 0) out[b * C_ + cc] = acc + fc2_b[cc];
    }
}

// ---------------- launch ----------------
extern "C" void kernel_launch(void* const* d_in, const int* in_sizes, int n_in,
                              void* d_out, int out_size) {
    const float* x      = (const float*)d_in[0];
    const float* Wih_f  = (const float*)d_in[1];
    const float* Whh_f  = (const float*)d_in[2];
    const float* bih_f  = (const float*)d_in[3];
    const float* bhh_f  = (const float*)d_in[4];
    const float* Wih_b  = (const float*)d_in[5];
    const float* Whh_b  = (const float*)d_in[6];
    const float* bih_b  = (const float*)d_in[7];
    const float* bhh_b  = (const float*)d_in[8];
    const float* attn_w = (const float*)d_in[9];
    const float* attn_b = (const float*)d_in[10];
    const float* fc1_w  = (const float*)d_in[11];
    const float* fc1_b  = (const float*)d_in[12];
    const float* fc2_w  = (const float*)d_in[13];
    const float* fc2_b  = (const float*)d_in[14];
    float* out = (float*)d_out;

    prep_x<<<M_ / 2, 2 * KP>>>(x);
    prep_w<<<N_, KP>>>(Wih_f, Wih_b);
    gemm_hmma<<<dim3(N_ / BN, M_ / BM), 256>>>(bih_f, bhh_f, bih_b, bhh_b);

    lstm_scan_mma<<<32, 512>>>(Whh_f, Whh_b);

    attn_mlp<<<B_, 256>>>(attn_w, attn_b, fc1_w, fc1_b, fc2_w, fc2_b, out);
}

// round 15
// speedup vs baseline: 1.4269x; 1.0346x over previous
// R15: resubmit of R14 (broker flake — never executed; aliasing re-audited).
// GEMM epilogue staged through smem (aliased As) for coalesced STG.128;
// prep_x+prep_w merged. Scan unchanged from R13 (best measured: 426us).
#include <cuda_runtime.h>
#include <cuda_fp16.h>
#include <cstdint>
#include <cstddef>

#define T_  512
#define B_  128
#define E_  300
#define H_  128
#define G4  512
#define KP  320
#define M_  (T_*B_)
#define N_  1024
#define FC1_ 256
#define C_  5

__device__ __half g_xh[(size_t)M_ * KP];
__device__ __half g_wcat[(size_t)N_ * KP];    // permuted rows
__device__ __half g_xg[(size_t)N_ * M_];      // fp16 preacts+bias, layout [n_perm][t*B+b]
__device__ float  g_hf[(size_t)T_ * B_ * H_];
__device__ float  g_hb[(size_t)T_ * B_ * H_];

__host__ __device__ __forceinline__ int perm_src(int p) {
    int r = p & 15;
    int g = ((r >> 3) << 1) | (r & 1);
    int u = (p >> 4) * 4 + ((r >> 1) & 3);
    return g * 128 + u;
}

// ---------------- prep (merged) ----------------
__global__ void prep_all(const float* __restrict__ x,
                         const float* __restrict__ wf, const float* __restrict__ wb) {
    int bid = blockIdx.x;
    int e = threadIdx.x >= KP ? threadIdx.x - KP : threadIdx.x;
    if (bid < M_ / 2) {
        int m = bid * 2 + (threadIdx.x >= KP);
        int t = m >> 7;
        int b = m & 127;
        float v = (e < E_) ? x[((size_t)b * T_ + t) * E_ + e] : 0.f;
        g_xh[(size_t)m * KP + e] = __float2half_rn(v);
    } else {
        int n = (bid - M_ / 2) * 2 + (threadIdx.x >= KP);
        int src = perm_src(n & 511);
        float v = 0.f;
        if (e < E_) v = (n < G4) ? wf[(size_t)src * E_ + e] : wb[(size_t)src * E_ + e];
        g_wcat[(size_t)n * KP + e] = __float2half_rn(v);
    }
}

// ---------------- input GEMM ----------------
#define BM 128
#define BN 64
#define BK 32
#define SSTR (BK + 8)
#define EPSTR 136   // epilogue smem stride (halves)

__global__ __launch_bounds__(256) void gemm_hmma(
    const float* __restrict__ bih_f, const float* __restrict__ bhh_f,
    const float* __restrict__ bih_b, const float* __restrict__ bhh_b) {
    __shared__ __align__(16) __half As[2][BM][SSTR];
    __shared__ __align__(16) __half Bs[2][BN][SSTR];

    int tid  = threadIdx.x;
    int wid  = tid >> 5;
    int lane = tid & 31;
    int wm   = wid >> 1;
    int wn   = wid & 1;
    int bm   = blockIdx.y * BM;
    int bn   = blockIdx.x * BN;

    float acc[2][4][4];
#pragma unroll
    for (int i = 0; i < 2; i++)
#pragma unroll
        for (int j = 0; j < 4; j++)
#pragma unroll
            for (int k = 0; k < 4; k++) acc[i][j][k] = 0.f;

    int ar = tid >> 2;
    int ac = (tid & 3) * 8;

    uint4 ra0, ra1, rb0;
    {
        ra0 = *(const uint4*)&g_xh[(size_t)(bm + ar)      * KP + ac];
        ra1 = *(const uint4*)&g_xh[(size_t)(bm + 64 + ar) * KP + ac];
        rb0 = *(const uint4*)&g_wcat[(size_t)(bn + ar)    * KP + ac];
        *(uint4*)&As[0][ar][ac]      = ra0;
        *(uint4*)&As[0][64 + ar][ac] = ra1;
        *(uint4*)&Bs[0][ar][ac]      = rb0;
    }
    __syncthreads();

    const int NIT = KP / BK;
    for (int it = 0; it < NIT; ++it) {
        int cur = it & 1;
        bool pf = (it + 1 < NIT);
        if (pf) {
            int k0 = (it + 1) * BK;
            ra0 = *(const uint4*)&g_xh[(size_t)(bm + ar)      * KP + k0 + ac];
            ra1 = *(const uint4*)&g_xh[(size_t)(bm + 64 + ar) * KP + k0 + ac];
            rb0 = *(const uint4*)&g_wcat[(size_t)(bn + ar)    * KP + k0 + ac];
        }
#pragma unroll
        for (int kk = 0; kk < 2; ++kk) {
            uint32_t a[2][4], bf[4][2];
#pragma unroll
            for (int mf = 0; mf < 2; ++mf) {
                int row = wm * 32 + mf * 16 + (lane & 15);
                int ko  = kk * 16 + (lane >> 4) * 8;
                unsigned sa = (unsigned)__cvta_generic_to_shared(&As[cur][row][ko]);
                asm volatile("ldmatrix.sync.aligned.m8n8.x4.shared.b16 {%0,%1,%2,%3}, [%4];"
                             : "=r"(a[mf][0]), "=r"(a[mf][1]), "=r"(a[mf][2]), "=r"(a[mf][3])
                             : "r"(sa));
            }
#pragma unroll
            for (int nf = 0; nf < 4; ++nf) {
                int row = wn * 32 + nf * 8 + (lane & 7);
                int ko  = kk * 16 + ((lane >> 3) & 1) * 8;
                unsigned sb = (unsigned)__cvta_generic_to_shared(&Bs[cur][row][ko]);
                asm volatile("ldmatrix.sync.aligned.m8n8.x2.shared.b16 {%0,%1}, [%2];"
                             : "=r"(bf[nf][0]), "=r"(bf[nf][1])
                             : "r"(sb));
            }
#pragma unroll
            for (int mf = 0; mf < 2; ++mf)
#pragma unroll
                for (int nf = 0; nf < 4; ++nf)
                    asm volatile(
                        "mma.sync.aligned.m16n8k16.row.col.f32.f16.f16.f32 "
                        "{%0,%1,%2,%3},{%4,%5,%6,%7},{%8,%9},{%0,%1,%2,%3};"
                        : "+f"(acc[mf][nf][0]), "+f"(acc[mf][nf][1]),
                          "+f"(acc[mf][nf][2]), "+f"(acc[mf][nf][3])
                        : "r"(a[mf][0]), "r"(a[mf][1]), "r"(a[mf][2]), "r"(a[mf][3]),
                          "r"(bf[nf][0]), "r"(bf[nf][1]));
        }
        __syncthreads();
        if (pf) {
            int nxt = 1 - cur;
            *(uint4*)&As[nxt][ar][ac]      = ra0;
            *(uint4*)&As[nxt][64 + ar][ac] = ra1;
            *(uint4*)&Bs[nxt][ar][ac]      = rb0;
        }
        __syncthreads();
    }

    // epilogue: bias add, stage fp16 tile in smem (alias dead As), coalesced stores
    float bb[4][2];
#pragma unroll
    for (int nf = 0; nf < 4; ++nf) {
#pragma unroll
        for (int h = 0; h < 2; ++h) {
            int col = bn + wn * 32 + nf * 8 + (lane & 3) * 2 + h;
            int src = perm_src(col & 511);
            bb[nf][h] = (col < G4) ? (bih_f[src] + bhh_f[src])
                                   : (bih_b[src] + bhh_b[src]);
        }
    }
    __half* S = (__half*)As;   // 64 rows (n) x EPSTR halves; 17.4KB < 20.5KB
#pragma unroll
    for (int mf = 0; mf < 2; ++mf)
#pragma unroll
        for (int nf = 0; nf < 4; ++nf) {
            int rl = wm * 32 + mf * 16 + (lane >> 2);
            int cl = wn * 32 + nf * 8 + (lane & 3) * 2;
            S[cl * EPSTR + rl]           = __float2half_rn(acc[mf][nf][0] + bb[nf][0]);
            S[(cl + 1) * EPSTR + rl]     = __float2half_rn(acc[mf][nf][1] + bb[nf][1]);
            S[cl * EPSTR + rl + 8]       = __float2half_rn(acc[mf][nf][2] + bb[nf][0]);
            S[(cl + 1) * EPSTR + rl + 8] = __float2half_rn(acc[mf][nf][3] + bb[nf][1]);
        }
    __syncthreads();
#pragma unroll
    for (int q = 0; q < 4; ++q) {
        int idx = q * 256 + tid;
        int cc = idx >> 4;          // 0..63 (n within tile)
        int xx = idx & 15;          // 16B chunk within the 128-half row
        uint4 v = *(const uint4*)&S[cc * EPSTR + xx * 8];
        *(uint4*)&g_xg[(size_t)(bn + cc) * M_ + bm + xx * 8] = v;
    }
}

// ---------------- tensor-core LSTM scan (batch on n) — unchanged ----------------
__device__ __forceinline__ float tanh_t(float x) {
    float r; asm("tanh.approx.f32 %0, %1;" : "=f"(r) : "f"(x)); return r;
}
__device__ __forceinline__ float sig_t(float x) {
    return fmaf(tanh_t(0.5f * x), 0.5f, 0.5f);
}

#define NB 8

__global__ __launch_bounds__(512, 1) void lstm_scan_mma(
    const float* __restrict__ Whh_f, const float* __restrict__ Whh_b) {
    __shared__ __align__(16) __half sh[2][H_][NB];

    int tid = threadIdx.x;
    int w   = tid >> 5;
    int l   = tid & 31;
    int c   = l & 3;
    int rg  = l >> 2;
    int dir = blockIdx.x >> 4;
    int b0  = (blockIdx.x & 15) * NB;
    const float* Whh = dir ? Whh_b : Whh_f;
    float* hout = dir ? g_hb : g_hf;
    int myp = rg & 1;
    int bat = c * 2 + myp;
    int uloc = rg >> 1;

    uint32_t afr[2][8][4];
#pragma unroll
    for (int mt = 0; mt < 2; mt++) {
        int tau = w * 2 + mt;
        int o1 = (myp)     * 128 + tau * 4 + uloc;
        int o2 = (myp + 2) * 128 + tau * 4 + uloc;
        const float* w1 = Whh + (size_t)o1 * H_;
        const float* w2 = Whh + (size_t)o2 * H_;
#pragma unroll
        for (int kt = 0; kt < 8; kt++) {
            int k = kt * 16 + c * 2;
            float2 p0 = *(const float2*)&w1[k];
            float2 p1 = *(const float2*)&w2[k];
            float2 p2 = *(const float2*)&w1[k + 8];
            float2 p3 = *(const float2*)&w2[k + 8];
            __half2 h0 = __floats2half2_rn(p0.x, p0.y);
            __half2 h1 = __floats2half2_rn(p1.x, p1.y);
            __half2 h2 = __floats2half2_rn(p2.x, p2.y);
            __half2 h3 = __floats2half2_rn(p3.x, p3.y);
            afr[mt][kt][0] = *(uint32_t*)&h0;
            afr[mt][kt][1] = *(uint32_t*)&h1;
            afr[mt][kt][2] = *(uint32_t*)&h2;
            afr[mt][kt][3] = *(uint32_t*)&h3;
        }
    }

    for (int i = tid; i < 2 * H_ * NB; i += 512) ((__half*)sh)[i] = __float2half(0.f);

    const size_t nbase = (size_t)(dir * G4 + w * 32);
    uint32_t xr[2][2];
    {
        int tt = dir ? (T_ - 1) : 0;
        size_t mo = (size_t)tt * B_ + b0 + c * 2;
#pragma unroll
        for (int mt = 0; mt < 2; mt++) {
            xr[mt][0] = *(const uint32_t*)&g_xg[(nbase + mt * 16 + rg)     * M_ + mo];
            xr[mt][1] = *(const uint32_t*)&g_xg[(nbase + mt * 16 + rg + 8) * M_ + mo];
        }
    }

    float cst[2] = {0.f, 0.f};
    __syncthreads();

    for (int s = 0; s < T_; ++s) {
        int tt = dir ? (T_ - 1 - s) : s;

        float d[2][4];
#pragma unroll
        for (int mt = 0; mt < 2; mt++) {
            float2 lo = __half22float2(*(__half2*)&xr[mt][0]);
            float2 hi = __half22float2(*(__half2*)&xr[mt][1]);
            d[mt][0] = lo.x; d[mt][1] = lo.y; d[mt][2] = hi.x; d[mt][3] = hi.y;
        }

        if (s + 1 < T_) {
            int tn = dir ? (T_ - 2 - s) : (s + 1);
            size_t mo = (size_t)tn * B_ + b0 + c * 2;
#pragma unroll
            for (int mt = 0; mt < 2; mt++) {
                xr[mt][0] = *(const uint32_t*)&g_xg[(nbase + mt * 16 + rg)     * M_ + mo];
                xr[mt][1] = *(const uint32_t*)&g_xg[(nbase + mt * 16 + rg + 8) * M_ + mo];
            }
        }

        uint32_t bfr[8][2];
#pragma unroll
        for (int kt = 0; kt < 8; kt++) {
            unsigned sb = (unsigned)__cvta_generic_to_shared(&sh[s & 1][kt * 16 + (l & 15)][0]);
            asm volatile("ldmatrix.sync.aligned.m8n8.x2.trans.shared.b16 {%0,%1}, [%2];"
                         : "=r"(bfr[kt][0]), "=r"(bfr[kt][1]) : "r"(sb));
        }
#pragma unroll
        for (int mt = 0; mt < 2; mt++)
#pragma unroll
            for (int kt = 0; kt < 8; kt++)
                asm volatile(
                    "mma.sync.aligned.m16n8k16.row.col.f32.f16.f16.f32 "
                    "{%0,%1,%2,%3},{%4,%5,%6,%7},{%8,%9},{%0,%1,%2,%3};"
                    : "+f"(d[mt][0]), "+f"(d[mt][1]), "+f"(d[mt][2]), "+f"(d[mt][3])
                    : "r"(afr[mt][kt][0]), "r"(afr[mt][kt][1]),
                      "r"(afr[mt][kt][2]), "r"(afr[mt][kt][3]),
                      "r"(bfr[kt][0]), "r"(bfr[kt][1]));

#pragma unroll
        for (int mt = 0; mt < 2; mt++) {
            float alo_b0 = sig_t(d[mt][0]);
            float alo_b1 = sig_t(d[mt][1]);
            float ahi_b0 = myp ? sig_t(d[mt][2]) : tanh_t(d[mt][2]);
            float ahi_b1 = myp ? sig_t(d[mt][3]) : tanh_t(d[mt][3]);
            float mine_lo = myp ? alo_b1 : alo_b0;
            float mine_hi = myp ? ahi_b1 : ahi_b0;
            float send_lo = myp ? alo_b0 : alo_b1;
            float send_hi = myp ? ahi_b0 : ahi_b1;
            float rec_lo = __shfl_xor_sync(0xffffffffu, send_lo, 4);
            float rec_hi = __shfl_xor_sync(0xffffffffu, send_hi, 4);
            float ii = myp ? rec_lo  : mine_lo;
            float gg = myp ? rec_hi  : mine_hi;
            float ff = myp ? mine_lo : rec_lo;
            float oo = myp ? mine_hi : rec_hi;
            float cn = fmaf(ff, cst[mt], ii * gg);
            cst[mt] = cn;
            float hh = oo * tanh_t(cn);
            int unit = (w * 2 + mt) * 4 + uloc;
            sh[(s + 1) & 1][unit][bat] = __float2half_rn(hh);
            hout[((size_t)tt * B_ + b0 + bat) * H_ + unit] = hh;
        }
        __syncthreads();
    }
}

// ---------------- attention pooling + MLP head ----------------
__global__ __launch_bounds__(256) void attn_mlp(
    const float* __restrict__ attn_w, const float* __restrict__ attn_b,
    const float* __restrict__ fc1_w, const float* __restrict__ fc1_b,
    const float* __restrict__ fc2_w, const float* __restrict__ fc2_b,
    float* __restrict__ out) {
    __shared__ float aw[256];
    __shared__ float sl[512];
    __shared__ float red[256];
    __shared__ float sp[256];
    __shared__ float sh1[256];

    int b = blockIdx.x, tid = threadIdx.x;
    aw[tid] = attn_w[tid];
    __syncthreads();
    float ab = attn_b[0];

#pragma unroll
    for (int r = 0; r < 2; r++) {
        int t = tid + r * 256;
        const float4* pf = (const float4*)&g_hf[((size_t)t * B_ + b) * H_];
        const float4* pb = (const float4*)&g_hb[((size_t)t * B_ + b) * H_];
        const float4* wf = (const float4*)aw;
        const float4* wb = (const float4*)(aw + 128);
        float acc = 0.f;
#pragma unroll 8
        for (int qq = 0; qq < 32; qq++) {
            float4 a = pf[qq]; float4 w = wf[qq];
            acc += a.x * w.x + a.y * w.y + a.z * w.z + a.w * w.w;
        }
#pragma unroll 8
        for (int qq = 0; qq < 32; qq++) {
            float4 a = pb[qq]; float4 w = wb[qq];
            acc += a.x * w.x + a.y * w.y + a.z * w.z + a.w * w.w;
        }
        sl[t] = acc + ab;
    }
    __syncthreads();

    red[tid] = fmaxf(sl[tid], sl[tid + 256]);
    __syncthreads();
    for (int st = 128; st > 0; st >>= 1) {
        if (tid < st) red[tid] = fmaxf(red[tid], red[tid + st]);
        __syncthreads();
    }
    float mx = red[0];
    __syncthreads();
    float e0 = __expf(sl[tid] - mx), e1 = __expf(sl[tid + 256] - mx);
    sl[tid] = e0; sl[tid + 256] = e1;
    red[tid] = e0 + e1;
    __syncthreads();
    for (int st = 128; st > 0; st >>= 1) {
        if (tid < st) red[tid] += red[tid + st];
        __syncthreads();
    }
    float inv = 1.f / red[0];
    __syncthreads();

    {
        const float* src = (tid < 128) ? g_hf : g_hb;
        int u = tid & 127;
        float a0 = 0, a1 = 0, a2 = 0, a3 = 0;
        for (int t = 0; t < 512; t += 4) {
            a0 += sl[t    ] * src[((size_t)(t    ) * B_ + b) * H_ + u];
            a1 += sl[t + 1] * src[((size_t)(t + 1) * B_ + b) * H_ + u];
            a2 += sl[t + 2] * src[((size_t)(t + 2) * B_ + b) * H_ + u];
            a3 += sl[t + 3] * src[((size_t)(t + 3) * B_ + b) * H_ + u];
        }
        sp[tid] = (a0 + a1 + a2 + a3) * inv;
    }
    __syncthreads();

    {
        const float4* w = (const float4*)&fc1_w[(size_t)tid * 256];
        const float4* p = (const float4*)sp;
        float acc = fc1_b[tid];
#pragma unroll 8
        for (int qq = 0; qq < 64; qq++) {
            float4 a = p[qq]; float4 ww = w[qq];
            acc += a.x * ww.x + a.y * ww.y + a.z * ww.z + a.w * ww.w;
        }
        sh1[tid] = fmaxf(acc, 0.f);
    }
    __syncthreads();

    if (tid < 160) {
        int cc = tid >> 5, lane = tid & 31;
        float acc = 0.f;
        for (int qq = lane; qq < 256; qq += 32) acc += sh1[qq] * fc2_w[(size_t)cc * 256 + qq];
#pragma unroll
        for (int o = 16; o > 0; o >>= 1) acc += __shfl_down_sync(0xffffffffu, acc, o);
        if (lane == 0) out[b * C_ + cc] = acc + fc2_b[cc];
    }
}

// ---------------- launch ----------------
extern "C" void kernel_launch(void* const* d_in, const int* in_sizes, int n_in,
                              void* d_out, int out_size) {
    const float* x      = (const float*)d_in[0];
    const float* Wih_f  = (const float*)d_in[1];
    const float* Whh_f  = (const float*)d_in[2];
    const float* bih_f  = (const float*)d_in[3];
    const float* bhh_f  = (const float*)d_in[4];
    const float* Wih_b  = (const float*)d_in[5];
    const float* Whh_b  = (const float*)d_in[6];
    const float* bih_b  = (const float*)d_in[7];
    const float* bhh_b  = (const float*)d_in[8];
    const float* attn_w = (const float*)d_in[9];
    const float* attn_b = (const float*)d_in[10];
    const float* fc1_w  = (const float*)d_in[11];
    const float* fc1_b  = (const float*)d_in[12];
    const float* fc2_w  = (const float*)d_in[13];
    const float* fc2_b  = (const float*)d_in[14];
    float* out = (float*)d_out;

    prep_all<<<M_ / 2 + N_ / 2, 2 * KP>>>(x, Wih_f, Wih_b);
    gemm_hmma<<<dim3(N_ / BN, M_ / BM), 256>>>(bih_f, bhh_f, bih_b, bhh_b);

    lstm_scan_mma<<<32, 512>>>(Whh_f, Whh_b);

    attn_mlp<<<B_, 256>>>(attn_w, attn_b, fc1_w, fc1_b, fc2_w, fc2_b, out);
}

// round 17
// speedup vs baseline: 1.4617x; 1.0244x over previous
// R17: tcgen05 unavailable (harness targets sm_100, not sm_100a — ptxas
// rejected it). GEMM rebuilt within mma.sync: 3-stage cp.async pipeline,
// BN=128 (warp tile 32x64), 1 barrier/iter. Scan/attn/prep unchanged.
#include <cuda_runtime.h>
#include <cuda_fp16.h>
#include <cstdint>
#include <cstddef>

#define T_  512
#define B_  128
#define E_  300
#define H_  128
#define G4  512
#define KP  320
#define M_  (T_*B_)
#define N_  1024
#define FC1_ 256
#define C_  5

__device__ __half g_xh[(size_t)M_ * KP];
__device__ __half g_wcat[(size_t)N_ * KP];    // permuted rows
__device__ __half g_xg[(size_t)N_ * M_];      // fp16 preacts+bias, layout [n_perm][t*B+b]
__device__ float  g_hf[(size_t)T_ * B_ * H_];
__device__ float  g_hb[(size_t)T_ * B_ * H_];

__host__ __device__ __forceinline__ int perm_src(int p) {
    int r = p & 15;
    int g = ((r >> 3) << 1) | (r & 1);
    int u = (p >> 4) * 4 + ((r >> 1) & 3);
    return g * 128 + u;
}

// ---------------- prep (merged) ----------------
__global__ void prep_all(const float* __restrict__ x,
                         const float* __restrict__ wf, const float* __restrict__ wb) {
    int bid = blockIdx.x;
    int e = threadIdx.x >= KP ? threadIdx.x - KP : threadIdx.x;
    if (bid < M_ / 2) {
        int m = bid * 2 + (threadIdx.x >= KP);
        int t = m >> 7;
        int b = m & 127;
        float v = (e < E_) ? x[((size_t)b * T_ + t) * E_ + e] : 0.f;
        g_xh[(size_t)m * KP + e] = __float2half_rn(v);
    } else {
        int n = (bid - M_ / 2) * 2 + (threadIdx.x >= KP);
        int src = perm_src(n & 511);
        float v = 0.f;
        if (e < E_) v = (n < G4) ? wf[(size_t)src * E_ + e] : wb[(size_t)src * E_ + e];
        g_wcat[(size_t)n * KP + e] = __float2half_rn(v);
    }
}

// ---------------- input GEMM (mma.sync, 3-stage cp.async) ----------------
#define BM 128
#define BN 128
#define BK 32
#define SSTR 40                  // smem stride in halves
#define STG_BYTES (128 * SSTR * 2)   // one tile (A or B): 10240 B
#define A_OFF(st) ((st) * STG_BYTES)
#define B_OFF(st) (3 * STG_BYTES + (st) * STG_BYTES)
#define GSM_TOTAL (6 * STG_BYTES)    // 61440 B
#define EPSTR 136

__device__ __forceinline__ void cpa16(uint32_t dst, const void* src) {
    asm volatile("cp.async.cg.shared.global [%0], [%1], 16;" :: "r"(dst), "l"(src));
}

__global__ __launch_bounds__(256) void gemm_hmma(
    const float* __restrict__ bih_f, const float* __restrict__ bhh_f,
    const float* __restrict__ bih_b, const float* __restrict__ bhh_b) {
    extern __shared__ __align__(16) char smem[];
    uint32_t sb;
    asm("{ .reg .u64 t; cvta.to.shared.u64 t, %1; cvt.u32.u64 %0, t; }" : "=r"(sb) : "l"(smem));

    int tid  = threadIdx.x;
    int wid  = tid >> 5;
    int lane = tid & 31;
    int wm   = wid >> 1;       // 0..3 -> 32-row warp tile
    int wn   = wid & 1;        // 0..1 -> 64-col warp tile
    int bm   = blockIdx.y * BM;
    int bn   = blockIdx.x * BN;

    float acc[2][8][4];
#pragma unroll
    for (int i = 0; i < 2; i++)
#pragma unroll
        for (int j = 0; j < 8; j++)
#pragma unroll
            for (int k = 0; k < 4; k++) acc[i][j][k] = 0.f;

    // load indices: 512 chunks of 16B per tile, 2 per thread
    int ar = tid >> 1;               // row 0..127
    int ac = (tid & 1) * 16;         // halves 0 or 16 (two 16B chunks each)

    // prologue: stages 0,1
#pragma unroll
    for (int ps = 0; ps < 2; ps++) {
        int k0 = ps * BK;
#pragma unroll
        for (int h = 0; h < 2; h++) {
            cpa16(sb + A_OFF(ps) + (uint32_t)ar * (SSTR * 2) + (ac + h * 8) * 2,
                  &g_xh[(size_t)(bm + ar) * KP + k0 + ac + h * 8]);
            cpa16(sb + B_OFF(ps) + (uint32_t)ar * (SSTR * 2) + (ac + h * 8) * 2,
                  &g_wcat[(size_t)(bn + ar) * KP + k0 + ac + h * 8]);
        }
        asm volatile("cp.async.commit_group;" ::: "memory");
    }

    const int NIT = KP / BK;   // 10
    for (int it = 0; it < NIT; ++it) {
        if (it < NIT - 1) asm volatile("cp.async.wait_group 1;" ::: "memory");
        else              asm volatile("cp.async.wait_group 0;" ::: "memory");
        __syncthreads();   // stage it%3 ready; all warps done with stage (it+2)%3

        // issue stage it+2 (overwrites stage (it-1)%3, safe after barrier)
        if (it + 2 < NIT) {
            int st = (it + 2) % 3;
            int k0 = (it + 2) * BK;
#pragma unroll
            for (int h = 0; h < 2; h++) {
                cpa16(sb + A_OFF(st) + (uint32_t)ar * (SSTR * 2) + (ac + h * 8) * 2,
                      &g_xh[(size_t)(bm + ar) * KP + k0 + ac + h * 8]);
                cpa16(sb + B_OFF(st) + (uint32_t)ar * (SSTR * 2) + (ac + h * 8) * 2,
                      &g_wcat[(size_t)(bn + ar) * KP + k0 + ac + h * 8]);
            }
            asm volatile("cp.async.commit_group;" ::: "memory");
        }

        int cur = it % 3;
#pragma unroll
        for (int kk = 0; kk < 2; ++kk) {
            uint32_t a[2][4], bf[8][2];
#pragma unroll
            for (int mf = 0; mf < 2; ++mf) {
                int row = wm * 32 + mf * 16 + (lane & 15);
                int ko  = kk * 16 + (lane >> 4) * 8;
                uint32_t sa = sb + A_OFF(cur) + (uint32_t)row * (SSTR * 2) + ko * 2;
                asm volatile("ldmatrix.sync.aligned.m8n8.x4.shared.b16 {%0,%1,%2,%3}, [%4];"
                             : "=r"(a[mf][0]), "=r"(a[mf][1]), "=r"(a[mf][2]), "=r"(a[mf][3])
                             : "r"(sa));
            }
#pragma unroll
            for (int nf = 0; nf < 8; ++nf) {
                int row = wn * 64 + nf * 8 + (lane & 7);
                int ko  = kk * 16 + ((lane >> 3) & 1) * 8;
                uint32_t sB = sb + B_OFF(cur) + (uint32_t)row * (SSTR * 2) + ko * 2;
                asm volatile("ldmatrix.sync.aligned.m8n8.x2.shared.b16 {%0,%1}, [%2];"
                             : "=r"(bf[nf][0]), "=r"(bf[nf][1])
                             : "r"(sB));
            }
#pragma unroll
            for (int mf = 0; mf < 2; ++mf)
#pragma unroll
                for (int nf = 0; nf < 8; ++nf)
                    asm volatile(
                        "mma.sync.aligned.m16n8k16.row.col.f32.f16.f16.f32 "
                        "{%0,%1,%2,%3},{%4,%5,%6,%7},{%8,%9},{%0,%1,%2,%3};"
                        : "+f"(acc[mf][nf][0]), "+f"(acc[mf][nf][1]),
                          "+f"(acc[mf][nf][2]), "+f"(acc[mf][nf][3])
                        : "r"(a[mf][0]), "r"(a[mf][1]), "r"(a[mf][2]), "r"(a[mf][3]),
                          "r"(bf[nf][0]), "r"(bf[nf][1]));
        }
    }
    __syncthreads();

    // epilogue: bias add, stage fp16 tile [n=128][m=128] in smem, coalesced stores
    float bb[8][2];
#pragma unroll
    for (int nf = 0; nf < 8; ++nf) {
#pragma unroll
        for (int h = 0; h < 2; ++h) {
            int col = bn + wn * 64 + nf * 8 + (lane & 3) * 2 + h;
            int src = perm_src(col & 511);
            bb[nf][h] = (col < G4) ? (bih_f[src] + bhh_f[src])
                                   : (bih_b[src] + bhh_b[src]);
        }
    }
    __half* S = (__half*)smem;   // 128 x EPSTR halves = 34816 B < 61440
#pragma unroll
    for (int mf = 0; mf < 2; ++mf)
#pragma unroll
        for (int nf = 0; nf < 8; ++nf) {
            int rl = wm * 32 + mf * 16 + (lane >> 2);
            int cl = wn * 64 + nf * 8 + (lane & 3) * 2;
            S[cl * EPSTR + rl]           = __float2half_rn(acc[mf][nf][0] + bb[nf][0]);
            S[(cl + 1) * EPSTR + rl]     = __float2half_rn(acc[mf][nf][1] + bb[nf][1]);
            S[cl * EPSTR + rl + 8]       = __float2half_rn(acc[mf][nf][2] + bb[nf][0]);
            S[(cl + 1) * EPSTR + rl + 8] = __float2half_rn(acc[mf][nf][3] + bb[nf][1]);
        }
    __syncthreads();
#pragma unroll
    for (int q = 0; q < 8; ++q) {
        int idx = q * 256 + tid;
        int cc = idx >> 4;          // 0..127 (n within tile)
        int xx = idx & 15;          // 16B chunk within the 128-half m-row
        uint4 v = *(const uint4*)&S[cc * EPSTR + xx * 8];
        *(uint4*)&g_xg[(size_t)(bn + cc) * M_ + bm + xx * 8] = v;
    }
}

// ---------------- tensor-core LSTM scan (batch on n) — unchanged ----------------
__device__ __forceinline__ float tanh_t(float x) {
    float r; asm("tanh.approx.f32 %0, %1;" : "=f"(r) : "f"(x)); return r;
}
__device__ __forceinline__ float sig_t(float x) {
    return fmaf(tanh_t(0.5f * x), 0.5f, 0.5f);
}

#define NB 8

__global__ __launch_bounds__(512, 1) void lstm_scan_mma(
    const float* __restrict__ Whh_f, const float* __restrict__ Whh_b) {
    __shared__ __align__(16) __half sh[2][H_][NB];

    int tid = threadIdx.x;
    int w   = tid >> 5;
    int l   = tid & 31;
    int c   = l & 3;
    int rg  = l >> 2;
    int dir = blockIdx.x >> 4;
    int b0  = (blockIdx.x & 15) * NB;
    const float* Whh = dir ? Whh_b : Whh_f;
    float* hout = dir ? g_hb : g_hf;
    int myp = rg & 1;
    int bat = c * 2 + myp;
    int uloc = rg >> 1;

    uint32_t afr[2][8][4];
#pragma unroll
    for (int mt = 0; mt < 2; mt++) {
        int tau = w * 2 + mt;
        int o1 = (myp)     * 128 + tau * 4 + uloc;
        int o2 = (myp + 2) * 128 + tau * 4 + uloc;
        const float* w1 = Whh + (size_t)o1 * H_;
        const float* w2 = Whh + (size_t)o2 * H_;
#pragma unroll
        for (int kt = 0; kt < 8; kt++) {
            int k = kt * 16 + c * 2;
            float2 p0 = *(const float2*)&w1[k];
            float2 p1 = *(const float2*)&w2[k];
            float2 p2 = *(const float2*)&w1[k + 8];
            float2 p3 = *(const float2*)&w2[k + 8];
            __half2 h0 = __floats2half2_rn(p0.x, p0.y);
            __half2 h1 = __floats2half2_rn(p1.x, p1.y);
            __half2 h2 = __floats2half2_rn(p2.x, p2.y);
            __half2 h3 = __floats2half2_rn(p3.x, p3.y);
            afr[mt][kt][0] = *(uint32_t*)&h0;
            afr[mt][kt][1] = *(uint32_t*)&h1;
            afr[mt][kt][2] = *(uint32_t*)&h2;
            afr[mt][kt][3] = *(uint32_t*)&h3;
        }
    }

    for (int i = tid; i < 2 * H_ * NB; i += 512) ((__half*)sh)[i] = __float2half(0.f);

    const size_t nbase = (size_t)(dir * G4 + w * 32);
    uint32_t xr[2][2];
    {
        int tt = dir ? (T_ - 1) : 0;
        size_t mo = (size_t)tt * B_ + b0 + c * 2;
#pragma unroll
        for (int mt = 0; mt < 2; mt++) {
            xr[mt][0] = *(const uint32_t*)&g_xg[(nbase + mt * 16 + rg)     * M_ + mo];
            xr[mt][1] = *(const uint32_t*)&g_xg[(nbase + mt * 16 + rg + 8) * M_ + mo];
        }
    }

    float cst[2] = {0.f, 0.f};
    __syncthreads();

    for (int s = 0; s < T_; ++s) {
        int tt = dir ? (T_ - 1 - s) : s;

        float d[2][4];
#pragma unroll
        for (int mt = 0; mt < 2; mt++) {
            float2 lo = __half22float2(*(__half2*)&xr[mt][0]);
            float2 hi = __half22float2(*(__half2*)&xr[mt][1]);
            d[mt][0] = lo.x; d[mt][1] = lo.y; d[mt][2] = hi.x; d[mt][3] = hi.y;
        }

        if (s + 1 < T_) {
            int tn = dir ? (T_ - 2 - s) : (s + 1);
            size_t mo = (size_t)tn * B_ + b0 + c * 2;
#pragma unroll
            for (int mt = 0; mt < 2; mt++) {
                xr[mt][0] = *(const uint32_t*)&g_xg[(nbase + mt * 16 + rg)     * M_ + mo];
                xr[mt][1] = *(const uint32_t*)&g_xg[(nbase + mt * 16 + rg + 8) * M_ + mo];
            }
        }

        uint32_t bfr[8][2];
#pragma unroll
        for (int kt = 0; kt < 8; kt++) {
            unsigned sbm = (unsigned)__cvta_generic_to_shared(&sh[s & 1][kt * 16 + (l & 15)][0]);
            asm volatile("ldmatrix.sync.aligned.m8n8.x2.trans.shared.b16 {%0,%1}, [%2];"
                         : "=r"(bfr[kt][0]), "=r"(bfr[kt][1]) : "r"(sbm));
        }
#pragma unroll
        for (int mt = 0; mt < 2; mt++)
#pragma unroll
            for (int kt = 0; kt < 8; kt++)
                asm volatile(
                    "mma.sync.aligned.m16n8k16.row.col.f32.f16.f16.f32 "
                    "{%0,%1,%2,%3},{%4,%5,%6,%7},{%8,%9},{%0,%1,%2,%3};"
                    : "+f"(d[mt][0]), "+f"(d[mt][1]), "+f"(d[mt][2]), "+f"(d[mt][3])
                    : "r"(afr[mt][kt][0]), "r"(afr[mt][kt][1]),
                      "r"(afr[mt][kt][2]), "r"(afr[mt][kt][3]),
                      "r"(bfr[kt][0]), "r"(bfr[kt][1]));

#pragma unroll
        for (int mt = 0; mt < 2; mt++) {
            float alo_b0 = sig_t(d[mt][0]);
            float alo_b1 = sig_t(d[mt][1]);
            float ahi_b0 = myp ? sig_t(d[mt][2]) : tanh_t(d[mt][2]);
            float ahi_b1 = myp ? sig_t(d[mt][3]) : tanh_t(d[mt][3]);
            float mine_lo = myp ? alo_b1 : alo_b0;
            float mine_hi = myp ? ahi_b1 : ahi_b0;
            float send_lo = myp ? alo_b0 : alo_b1;
            float send_hi = myp ? ahi_b0 : ahi_b1;
            float rec_lo = __shfl_xor_sync(0xffffffffu, send_lo, 4);
            float rec_hi = __shfl_xor_sync(0xffffffffu, send_hi, 4);
            float ii = myp ? rec_lo  : mine_lo;
            float gg = myp ? rec_hi  : mine_hi;
            float ff = myp ? mine_lo : rec_lo;
            float oo = myp ? mine_hi : rec_hi;
            float cn = fmaf(ff, cst[mt], ii * gg);
            cst[mt] = cn;
            float hh = oo * tanh_t(cn);
            int unit = (w * 2 + mt) * 4 + uloc;
            sh[(s + 1) & 1][unit][bat] = __float2half_rn(hh);
            hout[((size_t)tt * B_ + b0 + bat) * H_ + unit] = hh;
        }
        __syncthreads();
    }
}

// ---------------- attention pooling + MLP head ----------------
__global__ __launch_bounds__(256) void attn_mlp(
    const float* __restrict__ attn_w, const float* __restrict__ attn_b,
    const float* __restrict__ fc1_w, const float* __restrict__ fc1_b,
    const float* __restrict__ fc2_w, const float* __restrict__ fc2_b,
    float* __restrict__ out) {
    __shared__ float aw[256];
    __shared__ float sl[512];
    __shared__ float red[256];
    __shared__ float sp[256];
    __shared__ float sh1[256];

    int b = blockIdx.x, tid = threadIdx.x;
    aw[tid] = attn_w[tid];
    __syncthreads();
    float ab = attn_b[0];

#pragma unroll
    for (int r = 0; r < 2; r++) {
        int t = tid + r * 256;
        const float4* pf = (const float4*)&g_hf[((size_t)t * B_ + b) * H_];
        const float4* pb = (const float4*)&g_hb[((size_t)t * B_ + b) * H_];
        const float4* wf = (const float4*)aw;
        const float4* wb = (const float4*)(aw + 128);
        float acc = 0.f;
#pragma unroll 8
        for (int qq = 0; qq < 32; qq++) {
            float4 a = pf[qq]; float4 w = wf[qq];
            acc += a.x * w.x + a.y * w.y + a.z * w.z + a.w * w.w;
        }
#pragma unroll 8
        for (int qq = 0; qq < 32; qq++) {
            float4 a = pb[qq]; float4 w = wb[qq];
            acc += a.x * w.x + a.y * w.y + a.z * w.z + a.w * w.w;
        }
        sl[t] = acc + ab;
    }
    __syncthreads();

    red[tid] = fmaxf(sl[tid], sl[tid + 256]);
    __syncthreads();
    for (int st = 128; st > 0; st >>= 1) {
        if (tid < st) red[tid] = fmaxf(red[tid], red[tid + st]);
        __syncthreads();
    }
    float mx = red[0];
    __syncthreads();
    float e0 = __expf(sl[tid] - mx), e1 = __expf(sl[tid + 256] - mx);
    sl[tid] = e0; sl[tid + 256] = e1;
    red[tid] = e0 + e1;
    __syncthreads();
    for (int st = 128; st > 0; st >>= 1) {
        if (tid < st) red[tid] += red[tid + st];
        __syncthreads();
    }
    float inv = 1.f / red[0];
    __syncthreads();

    {
        const float* src = (tid < 128) ? g_hf : g_hb;
        int u = tid & 127;
        float a0 = 0, a1 = 0, a2 = 0, a3 = 0;
        for (int t = 0; t < 512; t += 4) {
            a0 += sl[t    ] * src[((size_t)(t    ) * B_ + b) * H_ + u];
            a1 += sl[t + 1] * src[((size_t)(t + 1) * B_ + b) * H_ + u];
            a2 += sl[t + 2] * src[((size_t)(t + 2) * B_ + b) * H_ + u];
            a3 += sl[t + 3] * src[((size_t)(t + 3) * B_ + b) * H_ + u];
        }
        sp[tid] = (a0 + a1 + a2 + a3) * inv;
    }
    __syncthreads();

    {
        const float4* w = (const float4*)&fc1_w[(size_t)tid * 256];
        const float4* p = (const float4*)sp;
        float acc = fc1_b[tid];
#pragma unroll 8
        for (int qq = 0; qq < 64; qq++) {
            float4 a = p[qq]; float4 ww = w[qq];
            acc += a.x * ww.x + a.y * ww.y + a.z * ww.z + a.w * ww.w;
        }
        sh1[tid] = fmaxf(acc, 0.f);
    }
    __syncthreads();

    if (tid < 160) {
        int cc = tid >> 5, lane = tid & 31;
        float acc = 0.f;
        for (int qq = lane; qq < 256; qq += 32) acc += sh1[qq] * fc2_w[(size_t)cc * 256 + qq];
#pragma unroll
        for (int o = 16; o > 0; o >>= 1) acc += __shfl_down_sync(0xffffffffu, acc, o);
        if (lane == 0) out[b * C_ + cc] = acc + fc2_b[cc];
    }
}

// ---------------- launch ----------------
extern "C" void kernel_launch(void* const* d_in, const int* in_sizes, int n_in,
                              void* d_out, int out_size) {
    const float* x      = (const float*)d_in[0];
    const float* Wih_f  = (const float*)d_in[1];
    const float* Whh_f  = (const float*)d_in[2];
    const float* bih_f  = (const float*)d_in[3];
    const float* bhh_f  = (const float*)d_in[4];
    const float* Wih_b  = (const float*)d_in[5];
    const float* Whh_b  = (const float*)d_in[6];
    const float* bih_b  = (const float*)d_in[7];
    const float* bhh_b  = (const float*)d_in[8];
    const float* attn_w = (const float*)d_in[9];
    const float* attn_b = (const float*)d_in[10];
    const float* fc1_w  = (const float*)d_in[11];
    const float* fc1_b  = (const float*)d_in[12];
    const float* fc2_w  = (const float*)d_in[13];
    const float* fc2_b  = (const float*)d_in[14];
    float* out = (float*)d_out;

    prep_all<<<M_ / 2 + N_ / 2, 2 * KP>>>(x, Wih_f, Wih_b);

    cudaFuncSetAttribute(gemm_hmma, cudaFuncAttributeMaxDynamicSharedMemorySize, GSM_TOTAL);
    gemm_hmma<<<dim3(N_ / BN, M_ / BM), 256, GSM_TOTAL>>>(bih_f, bhh_f, bih_b, bhh_b);

    lstm_scan_mma<<<32, 512>>>(Whh_f, Whh_b);

    attn_mlp<<<B_, 256>>>(attn_w, attn_b, fc1_w, fc1_b, fc2_w, fc2_b, out);
}